// round 8
// baseline (speedup 1.0000x reference)
#include <cuda_runtime.h>
#include <math.h>

#define TT 256
#define BB 256
#define DIN 129        // D+1
#define HH 512
#define GG 1536        // 3*H
#define N1 1280        // 10*D
#define K1 513         // H+1
#define DOUT 128
#define TM1 255        // T-1
#define M_PRE (BB*TM1) // 65280
#define OFF_DIST ((size_t)M_PRE*DOUT)            // 8,355,840
#define OFF_LEN  (OFF_DIST + (size_t)BB*3)       // 8,356,608

typedef unsigned long long u64t;

// ---------------- packed f32x2 helpers (Blackwell dual-fp32 path) ----------
__device__ __forceinline__ void ffma2(u64t &d, u64t a, u64t b){
    asm("fma.rn.f32x2 %0, %1, %2, %0;" : "+l"(d) : "l"(a), "l"(b));
}
__device__ __forceinline__ u64t pk2(float x, float y){
    u64t r; asm("mov.b64 %0, {%1,%2};" : "=l"(r) : "f"(x), "f"(y)); return r;
}
__device__ __forceinline__ float2 upk2(u64t v){
    float lo, hi; asm("mov.b64 {%0,%1}, %2;" : "=f"(lo), "=f"(hi) : "l"(v));
    return make_float2(lo, hi);
}

// ---------------- scratch (static device globals; no runtime allocation) ----
__device__ float g_xw[(size_t)TT*BB*GG];     // (t,b,g)
__device__ float g_hidden[(size_t)BB*TT*HH]; // (b,t,h)
__device__ float g_hA[BB*HH];
__device__ float g_hB[BB*HH];
__device__ float g_pre[(size_t)M_PRE*N1];    // (row,n)

__device__ __forceinline__ float sigmoidf_(float x){ return 1.0f/(1.0f+expf(-x)); }

// ---------------------------------------------------------------------------
// Kernel 1: xw[t,b,g] = sum_d x[t,b,d]*w_ih[g,d] + b_ih[g]
// ---------------------------------------------------------------------------
__global__ __launch_bounds__(256) void gemm_xw(
    const float* __restrict__ X, const float* __restrict__ W,
    const float* __restrict__ bias, float* __restrict__ out)
{
    __shared__ float As[32][68];
    __shared__ float Bs[32][68];
    const int bm = blockIdx.y*64;
    const int bn = blockIdx.x*64;
    const int tid = threadIdx.x;
    const int tx = tid & 15, ty = tid >> 4;
    u64t acc[4][2] = {};
    for (int k0 = 0; k0 < DIN; k0 += 32){
        #pragma unroll
        for (int i=0;i<8;i++){
            int idx = tid + i*256;
            int kk = idx & 31, mm = idx >> 5;
            As[kk][mm] = (k0+kk < DIN) ? X[(size_t)(bm+mm)*DIN + k0+kk] : 0.f;
        }
        #pragma unroll
        for (int i=0;i<8;i++){
            int idx = tid + i*256;
            int kk = idx & 31, nn = idx >> 5;
            Bs[kk][nn] = (k0+kk < DIN) ? W[(size_t)(bn+nn)*DIN + k0+kk] : 0.f;
        }
        __syncthreads();
        #pragma unroll
        for (int kk=0;kk<32;kk++){
            float4 a = *(const float4*)&As[kk][ty*4];
            ulonglong2 b = *(const ulonglong2*)&Bs[kk][tx*4];
            u64t pa0 = pk2(a.x,a.x), pa1 = pk2(a.y,a.y);
            u64t pa2 = pk2(a.z,a.z), pa3 = pk2(a.w,a.w);
            ffma2(acc[0][0], pa0, b.x); ffma2(acc[0][1], pa0, b.y);
            ffma2(acc[1][0], pa1, b.x); ffma2(acc[1][1], pa1, b.y);
            ffma2(acc[2][0], pa2, b.x); ffma2(acc[2][1], pa2, b.y);
            ffma2(acc[3][0], pa3, b.x); ffma2(acc[3][1], pa3, b.y);
        }
        __syncthreads();
    }
    #pragma unroll
    for (int i=0;i<4;i++){
        int m = bm + ty*4 + i;
        #pragma unroll
        for (int p=0;p<2;p++){
            float2 v = upk2(acc[i][p]);
            int n = bn + tx*4 + 2*p;
            out[(size_t)m*GG + n]     = v.x + bias[n];
            out[(size_t)m*GG + n + 1] = v.y + bias[n+1];
        }
    }
}

// ---------------------------------------------------------------------------
// Kernel 2: one GRU step, warp-owns-rows layout.
// grid (16 j-tiles, 8 b-tiles) = 128 CTAs, 256 thr (8 warps).
// Warp w: batch rows m0=4w..4w+3 (within 32-row tile); lane owns gate cols
// {bj+lane, 512+bj+lane, 1024+bj+lane}.  h staged transposed in smem
// hs[k][m] so a-operands are broadcast LDS.64 of m-pairs.  w streams from
// global (L1-shared across warps).  Per k: 2 bcast LDS.64 + 3 pk + 6 FFMA2.
// Epilogue entirely in registers: lane holds (r,z,n) for its 4 rows x 1 col.
// ---------------------------------------------------------------------------
#define GRU_SMEM (HH*32*4)   // 64 KB: hs[k][m]

__global__ __launch_bounds__(256) void gru_step(
    const float* __restrict__ xw_t, const float* __restrict__ h_prev,
    float* __restrict__ h_next, float* __restrict__ hidden,
    const float* __restrict__ w_hh, const float* __restrict__ b_hh,
    const int* __restrict__ lengths, int t)
{
    extern __shared__ float hs[];       // hs[k*32 + m]
    const int bj = blockIdx.x*32;       // gate-local column tile (0..480)
    const int bb = blockIdx.y*32;       // batch tile
    const int tid = threadIdx.x;

    // ---- stage h tile transposed: hs[k][m] ----
    {
        int m = tid & 31;
        int kbase = (tid >> 5) * 64;    // 8 groups x 64 k
        const float* src = &h_prev[(size_t)(bb+m)*HH + kbase];
        #pragma unroll
        for (int kk = 0; kk < 64; kk += 4){
            float4 v = *(const float4*)(src + kk);
            hs[(kbase+kk  )*32 + m] = v.x;
            hs[(kbase+kk+1)*32 + m] = v.y;
            hs[(kbase+kk+2)*32 + m] = v.z;
            hs[(kbase+kk+3)*32 + m] = v.w;
        }
    }
    __syncthreads();

    const int warp = tid >> 5;
    const int lane = tid & 31;
    const int m0   = warp * 4;          // 4 rows owned by this warp
    const int col  = bj + lane;         // gate-local column owned by this lane

    const float* w0p = w_hh + (size_t)(        col)*HH;  // r gate row
    const float* w1p = w_hh + (size_t)(HH   + col)*HH;   // z gate row
    const float* w2p = w_hh + (size_t)(2*HH + col)*HH;   // n gate row

    u64t acc[2][3] = {};                // [m-pair][gate]

    for (int k0 = 0; k0 < HH; k0 += 8){
        float4 wa0 = *(const float4*)(w0p + k0);
        float4 wb0 = *(const float4*)(w0p + k0 + 4);
        float4 wa1 = *(const float4*)(w1p + k0);
        float4 wb1 = *(const float4*)(w1p + k0 + 4);
        float4 wa2 = *(const float4*)(w2p + k0);
        float4 wb2 = *(const float4*)(w2p + k0 + 4);
        float w0v[8] = {wa0.x,wa0.y,wa0.z,wa0.w, wb0.x,wb0.y,wb0.z,wb0.w};
        float w1v[8] = {wa1.x,wa1.y,wa1.z,wa1.w, wb1.x,wb1.y,wb1.z,wb1.w};
        float w2v[8] = {wa2.x,wa2.y,wa2.z,wa2.w, wb2.x,wb2.y,wb2.z,wb2.w};
        #pragma unroll
        for (int j = 0; j < 8; j++){
            const float* hrow = &hs[(k0+j)*32 + m0];
            u64t a0 = *(const u64t*)(hrow);      // broadcast pair (m0,m0+1)
            u64t a1 = *(const u64t*)(hrow + 2);  // broadcast pair (m0+2,m0+3)
            u64t pw0 = pk2(w0v[j], w0v[j]);
            u64t pw1 = pk2(w1v[j], w1v[j]);
            u64t pw2 = pk2(w2v[j], w2v[j]);
            ffma2(acc[0][0], a0, pw0); ffma2(acc[1][0], a1, pw0);
            ffma2(acc[0][1], a0, pw1); ffma2(acc[1][1], a1, pw1);
            ffma2(acc[0][2], a0, pw2); ffma2(acc[1][2], a1, pw2);
        }
    }

    // ---- epilogue: all in registers, no smem exchange ----
    float2 r01 = upk2(acc[0][0]), r23 = upk2(acc[1][0]);
    float2 z01 = upk2(acc[0][1]), z23 = upk2(acc[1][1]);
    float2 n01 = upk2(acc[0][2]), n23 = upk2(acc[1][2]);
    float hrv[4] = {r01.x, r01.y, r23.x, r23.y};
    float hzv[4] = {z01.x, z01.y, z23.x, z23.y};
    float hnv[4] = {n01.x, n01.y, n23.x, n23.y};

    float br = b_hh[col], bz = b_hh[HH+col], bn = b_hh[2*HH+col];

    #pragma unroll
    for (int i = 0; i < 4; i++){
        int b  = bb + m0 + i;
        float xr = xw_t[(size_t)b*GG + col];
        float xz = xw_t[(size_t)b*GG + HH  + col];
        float xn = xw_t[(size_t)b*GG + 2*HH + col];
        float r = sigmoidf_(xr + hrv[i] + br);
        float z = sigmoidf_(xz + hzv[i] + bz);
        float n = tanhf(xn + r*(hnv[i] + bn));
        float hp = h_prev[(size_t)b*HH + col];
        bool valid = t < lengths[b];
        float hv = (1.f - z)*n + z*hp;
        h_next[(size_t)b*HH + col] = valid ? hv : hp;
        hidden[(size_t)b*(TT*HH) + (size_t)t*HH + col] = valid ? hv : 0.f;
    }
}

// ---------------------------------------------------------------------------
// Kernel 3: pre[row,n] = sigmoid( hwt[row,:] . w1[n,:] + b1[n] )
// ---------------------------------------------------------------------------
__global__ __launch_bounds__(256) void gemm_pre(
    const float* __restrict__ hidden, const float* __restrict__ X,
    const float* __restrict__ W1, const float* __restrict__ b1,
    float* __restrict__ pre)
{
    __shared__ float As[32][68];
    __shared__ float Bs[32][68];
    const int bm = blockIdx.y*64;
    const int bn = blockIdx.x*64;
    const int tid = threadIdx.x;
    const int tx = tid & 15, ty = tid >> 4;
    u64t acc[4][2] = {};
    for (int k0 = 0; k0 < K1; k0 += 32){
        #pragma unroll
        for (int i=0;i<8;i++){
            int idx = tid + i*256;
            int kk = idx & 31, mm = idx >> 5;
            int k = k0 + kk;
            int row = bm + mm;
            int b = row / TM1;
            int tt = row - b*TM1;
            float v = 0.f;
            if (k < HH){
                v = hidden[(size_t)b*(TT*HH) + (size_t)tt*HH + k];
            } else if (k == HH){
                v = X[(size_t)(tt+1)*BB*DIN + (size_t)b*DIN]
                  - X[(size_t)tt*BB*DIN + (size_t)b*DIN];
            }
            As[kk][mm] = v;
        }
        #pragma unroll
        for (int i=0;i<8;i++){
            int idx = tid + i*256;
            int kk = idx & 31, nn = idx >> 5;
            Bs[kk][nn] = (k0+kk < K1) ? W1[(size_t)(bn+nn)*K1 + k0+kk] : 0.f;
        }
        __syncthreads();
        #pragma unroll
        for (int kk=0;kk<32;kk++){
            float4 a = *(const float4*)&As[kk][ty*4];
            ulonglong2 b = *(const ulonglong2*)&Bs[kk][tx*4];
            u64t pa0 = pk2(a.x,a.x), pa1 = pk2(a.y,a.y);
            u64t pa2 = pk2(a.z,a.z), pa3 = pk2(a.w,a.w);
            ffma2(acc[0][0], pa0, b.x); ffma2(acc[0][1], pa0, b.y);
            ffma2(acc[1][0], pa1, b.x); ffma2(acc[1][1], pa1, b.y);
            ffma2(acc[2][0], pa2, b.x); ffma2(acc[2][1], pa2, b.y);
            ffma2(acc[3][0], pa3, b.x); ffma2(acc[3][1], pa3, b.y);
        }
        __syncthreads();
    }
    #pragma unroll
    for (int i=0;i<4;i++){
        int row = bm + ty*4 + i;
        #pragma unroll
        for (int p=0;p<2;p++){
            float2 v = upk2(acc[i][p]);
            int n = bn + tx*4 + 2*p;
            pre[(size_t)row*N1 + n]     = sigmoidf_(v.x + b1[n]);
            pre[(size_t)row*N1 + n + 1] = sigmoidf_(v.y + b1[n+1]);
        }
    }
}

// ---------------------------------------------------------------------------
// Kernel 4: preds[row,d] = mask ? pre[row,:] . w2[d,:] + b2[d] : 0
// ---------------------------------------------------------------------------
__global__ __launch_bounds__(256) void gemm_preds(
    const float* __restrict__ pre, const float* __restrict__ W2,
    const float* __restrict__ b2, const int* __restrict__ lengths,
    float* __restrict__ out)
{
    __shared__ float As[32][68];
    __shared__ float Bs[32][68];
    const int bm = blockIdx.y*64;
    const int bn = blockIdx.x*64;
    const int tid = threadIdx.x;
    const int tx = tid & 15, ty = tid >> 4;
    u64t acc[4][2] = {};
    for (int k0 = 0; k0 < N1; k0 += 32){
        #pragma unroll
        for (int i=0;i<8;i++){
            int idx = tid + i*256;
            int kk = idx & 31, mm = idx >> 5;
            As[kk][mm] = pre[(size_t)(bm+mm)*N1 + k0+kk];
        }
        #pragma unroll
        for (int i=0;i<8;i++){
            int idx = tid + i*256;
            int kk = idx & 31, nn = idx >> 5;
            Bs[kk][nn] = W2[(size_t)(bn+nn)*N1 + k0+kk];
        }
        __syncthreads();
        #pragma unroll
        for (int kk=0;kk<32;kk++){
            float4 a = *(const float4*)&As[kk][ty*4];
            ulonglong2 b = *(const ulonglong2*)&Bs[kk][tx*4];
            u64t pa0 = pk2(a.x,a.x), pa1 = pk2(a.y,a.y);
            u64t pa2 = pk2(a.z,a.z), pa3 = pk2(a.w,a.w);
            ffma2(acc[0][0], pa0, b.x); ffma2(acc[0][1], pa0, b.y);
            ffma2(acc[1][0], pa1, b.x); ffma2(acc[1][1], pa1, b.y);
            ffma2(acc[2][0], pa2, b.x); ffma2(acc[2][1], pa2, b.y);
            ffma2(acc[3][0], pa3, b.x); ffma2(acc[3][1], pa3, b.y);
        }
        __syncthreads();
    }
    #pragma unroll
    for (int i=0;i<4;i++){
        int row = bm + ty*4 + i;
        int b = row / TM1;
        int tt = row - b*TM1;
        bool m = tt < (lengths[b] - 1);
        #pragma unroll
        for (int p=0;p<2;p++){
            float2 v = upk2(acc[i][p]);
            int n = bn + tx*4 + 2*p;
            out[(size_t)row*DOUT + n]     = m ? (v.x + b2[n])   : 0.f;
            out[(size_t)row*DOUT + n + 1] = m ? (v.y + b2[n+1]) : 0.f;
        }
    }
}

// ---------------------------------------------------------------------------
// Kernel 5: dist head + lengths passthrough
// ---------------------------------------------------------------------------
__global__ __launch_bounds__(256) void finalize_k(
    const float* __restrict__ h_last, const float* __restrict__ wp,
    const float* __restrict__ bp, const int* __restrict__ lengths,
    float* __restrict__ out)
{
    int b = threadIdx.x;
    if (b < BB){
        #pragma unroll
        for (int p=0;p<3;p++){
            float dot = 0.f;
            for (int h=0;h<HH;h++) dot += h_last[b*HH + h]*wp[p*HH + h];
            out[OFF_DIST + (size_t)b*3 + p] = expf(-(dot + bp[p]));
        }
        out[OFF_LEN + b] = (float)lengths[b];
    }
}

// ---------------------------------------------------------------------------
extern "C" void kernel_launch(void* const* d_in, const int* in_sizes, int n_in,
                              void* d_out, int out_size)
{
    const float* x    = (const float*)d_in[0];
    const float* h0   = (const float*)d_in[1];
    const int*   len  = (const int*)d_in[2];
    const float* w_ih = (const float*)d_in[3];
    const float* w_hh = (const float*)d_in[4];
    const float* b_ih = (const float*)d_in[5];
    const float* b_hh = (const float*)d_in[6];
    const float* w1   = (const float*)d_in[7];
    const float* b1   = (const float*)d_in[8];
    const float* w2   = (const float*)d_in[9];
    const float* b2   = (const float*)d_in[10];
    const float* wp   = (const float*)d_in[11];
    const float* bp   = (const float*)d_in[12];
    float* out = (float*)d_out;

    float *xw, *hidden, *hA, *hB, *pre;
    cudaGetSymbolAddress((void**)&xw,     g_xw);
    cudaGetSymbolAddress((void**)&hidden, g_hidden);
    cudaGetSymbolAddress((void**)&hA,     g_hA);
    cudaGetSymbolAddress((void**)&hB,     g_hB);
    cudaGetSymbolAddress((void**)&pre,    g_pre);

    cudaFuncSetAttribute(gru_step,
        cudaFuncAttributeMaxDynamicSharedMemorySize, GRU_SMEM);

    // 1) input projection for all timesteps
    gemm_xw<<<dim3(GG/64, (TT*BB)/64), 256>>>(x, w_ih, b_ih, xw);

    // 2) sequential GRU with ping-pong h buffers
    const float* cur = h0;
    for (int t = 0; t < TT; t++){
        float* nxt = (t & 1) ? hB : hA;
        gru_step<<<dim3(16, 8), 256, GRU_SMEM>>>(
            xw + (size_t)t*BB*GG, cur, nxt, hidden, w_hh, b_hh, len, t);
        cur = nxt;
    }

    // 3) MLP head
    gemm_pre<<<dim3(N1/64, M_PRE/64), 256>>>(hidden, x, w1, b1, pre);
    gemm_preds<<<dim3(DOUT/64, M_PRE/64), 256>>>(pre, w2, b2, len, out);

    // 4) distribution head + lengths passthrough
    finalize_k<<<1, 256>>>(hB, wp, bp, len, out);
}

// round 9
// speedup vs baseline: 1.8512x; 1.8512x over previous
#include <cuda_runtime.h>
#include <math.h>

#define TT 256
#define BB 256
#define DIN 129        // D+1
#define HH 512
#define GG 1536        // 3*H
#define N1 1280        // 10*D
#define K1 513         // H+1
#define DOUT 128
#define TM1 255        // T-1
#define M_PRE (BB*TM1) // 65280
#define OFF_DIST ((size_t)M_PRE*DOUT)            // 8,355,840
#define OFF_LEN  (OFF_DIST + (size_t)BB*3)       // 8,356,608

typedef unsigned long long u64t;

// ---------------- packed f32x2 helpers (Blackwell dual-fp32 path) ----------
__device__ __forceinline__ void ffma2(u64t &d, u64t a, u64t b){
    asm("fma.rn.f32x2 %0, %1, %2, %0;" : "+l"(d) : "l"(a), "l"(b));
}
__device__ __forceinline__ u64t pk2(float x, float y){
    u64t r; asm("mov.b64 %0, {%1,%2};" : "=l"(r) : "f"(x), "f"(y)); return r;
}
__device__ __forceinline__ float2 upk2(u64t v){
    float lo, hi; asm("mov.b64 {%0,%1}, %2;" : "=f"(lo), "=f"(hi) : "l"(v));
    return make_float2(lo, hi);
}

// ---------------- scratch (static device globals; no runtime allocation) ----
__device__ float g_xw[(size_t)TT*BB*GG];     // (t,b,g)
__device__ float g_hidden[(size_t)BB*TT*HH]; // (b,t,h)
__device__ float g_hA[BB*HH];
__device__ float g_hB[BB*HH];
__device__ float g_pre[(size_t)M_PRE*N1];    // (row,n)

__device__ __forceinline__ float sigmoidf_(float x){ return 1.0f/(1.0f+expf(-x)); }

// ---------------------------------------------------------------------------
// Kernel 1: xw[t,b,g] = sum_d x[t,b,d]*w_ih[g,d] + b_ih[g]
// ---------------------------------------------------------------------------
__global__ __launch_bounds__(256) void gemm_xw(
    const float* __restrict__ X, const float* __restrict__ W,
    const float* __restrict__ bias, float* __restrict__ out)
{
    __shared__ __align__(16) float As[32][68];
    __shared__ __align__(16) float Bs[32][68];
    const int bm = blockIdx.y*64;
    const int bn = blockIdx.x*64;
    const int tid = threadIdx.x;
    const int tx = tid & 15, ty = tid >> 4;
    u64t acc[4][2] = {};
    for (int k0 = 0; k0 < DIN; k0 += 32){
        #pragma unroll
        for (int i=0;i<8;i++){
            int idx = tid + i*256;
            int kk = idx & 31, mm = idx >> 5;
            As[kk][mm] = (k0+kk < DIN) ? X[(size_t)(bm+mm)*DIN + k0+kk] : 0.f;
        }
        #pragma unroll
        for (int i=0;i<8;i++){
            int idx = tid + i*256;
            int kk = idx & 31, nn = idx >> 5;
            Bs[kk][nn] = (k0+kk < DIN) ? W[(size_t)(bn+nn)*DIN + k0+kk] : 0.f;
        }
        __syncthreads();
        #pragma unroll
        for (int kk=0;kk<32;kk++){
            float4 a = *(const float4*)&As[kk][ty*4];
            ulonglong2 b = *(const ulonglong2*)&Bs[kk][tx*4];
            u64t pa0 = pk2(a.x,a.x), pa1 = pk2(a.y,a.y);
            u64t pa2 = pk2(a.z,a.z), pa3 = pk2(a.w,a.w);
            ffma2(acc[0][0], pa0, b.x); ffma2(acc[0][1], pa0, b.y);
            ffma2(acc[1][0], pa1, b.x); ffma2(acc[1][1], pa1, b.y);
            ffma2(acc[2][0], pa2, b.x); ffma2(acc[2][1], pa2, b.y);
            ffma2(acc[3][0], pa3, b.x); ffma2(acc[3][1], pa3, b.y);
        }
        __syncthreads();
    }
    #pragma unroll
    for (int i=0;i<4;i++){
        int m = bm + ty*4 + i;
        #pragma unroll
        for (int p=0;p<2;p++){
            float2 v = upk2(acc[i][p]);
            int n = bn + tx*4 + 2*p;
            out[(size_t)m*GG + n]     = v.x + bias[n];
            out[(size_t)m*GG + n + 1] = v.y + bias[n+1];
        }
    }
}

// ---------------------------------------------------------------------------
// Kernel 2: one GRU step, fused 3-gate GEMM (32 batch x 96 gate-cols/CTA),
// DOUBLE-BUFFERED: register-staged prefetch of next k-chunk overlaps the
// current chunk's FFMA2 work; one barrier per chunk.  Epilogue operands
// (xw, h_prev, lengths, biases) prefetched into registers at kernel start.
// grid (16 j-tiles, 8 b-tiles) = 128 CTAs, 256 thr.
// ---------------------------------------------------------------------------
__global__ __launch_bounds__(256) void gru_step(
    const float* __restrict__ xw_t, const float* __restrict__ h_prev,
    float* __restrict__ h_next, float* __restrict__ hidden,
    const float* __restrict__ w_hh, const float* __restrict__ b_hh,
    const int* __restrict__ lengths, int t)
{
    __shared__ __align__(16) float hs[2][32][34];
    __shared__ __align__(16) float ws[2][32][98];
    const int bj = blockIdx.x*32;       // gate-local column tile (0..480)
    const int bb = blockIdx.y*32;       // batch tile
    const int tid = threadIdx.x;
    const int tx = tid & 15, ty = tid >> 4;

    // ---- epilogue operand prefetch (registers, issued before mainloop) ----
    const int jl_e = tid & 31;
    const int jj   = bj + jl_e;         // epilogue column (constant over q)
    float exr[4], exz[4], exn[4], ehp[4];
    int elen[4];
    #pragma unroll
    for (int q=0;q<4;q++){
        int m = (tid>>5) + q*8;
        int b = bb + m;
        exr[q]  = xw_t[(size_t)b*GG + jj];
        exz[q]  = xw_t[(size_t)b*GG + HH  + jj];
        exn[q]  = xw_t[(size_t)b*GG + 2*HH + jj];
        ehp[q]  = h_prev[(size_t)b*HH + jj];
        elen[q] = lengths[b];
    }
    const float br = b_hh[jj], bz = b_hh[HH+jj], bn = b_hh[2*HH+jj];

    u64t acc[2][3] = {};
    float hreg[4], wreg[12];

    // ---- prefetch chunk 0 (coalesced: 32 consecutive k per warp) ----
    #pragma unroll
    for (int i=0;i<4;i++){
        int idx = tid + i*256; int kk = idx & 31, m = idx >> 5;
        hreg[i] = h_prev[(size_t)(bb+m)*HH + kk];
    }
    #pragma unroll
    for (int i=0;i<12;i++){
        int idx = tid + i*256; int kk = idx & 31, c = idx >> 5;
        int g = c >> 5, jw = c & 31;
        wreg[i] = w_hh[(size_t)(g*HH + bj + jw)*HH + kk];
    }

    #pragma unroll 1
    for (int ch = 0; ch < 16; ch++){
        const int buf = ch & 1;
        // store prefetched regs into this chunk's buffer
        #pragma unroll
        for (int i=0;i<4;i++){
            int idx = tid + i*256; int kk = idx & 31, m = idx >> 5;
            hs[buf][kk][m] = hreg[i];
        }
        #pragma unroll
        for (int i=0;i<12;i++){
            int idx = tid + i*256; int kk = idx & 31, c = idx >> 5;
            ws[buf][kk][c] = wreg[i];
        }
        // issue next chunk's global loads (latency hidden behind compute)
        if (ch < 15){
            const int k0n = (ch+1)*32;
            #pragma unroll
            for (int i=0;i<4;i++){
                int idx = tid + i*256; int kk = idx & 31, m = idx >> 5;
                hreg[i] = h_prev[(size_t)(bb+m)*HH + k0n + kk];
            }
            #pragma unroll
            for (int i=0;i<12;i++){
                int idx = tid + i*256; int kk = idx & 31, c = idx >> 5;
                int g = c >> 5, jw = c & 31;
                wreg[i] = w_hh[(size_t)(g*HH + bj + jw)*HH + k0n + kk];
            }
        }
        __syncthreads();
        #pragma unroll
        for (int kk=0;kk<32;kk++){
            float2 a = *(const float2*)&hs[buf][kk][2*ty];
            u64t pa0 = pk2(a.x,a.x), pa1 = pk2(a.y,a.y);
            const float* wr = &ws[buf][kk][6*tx];
            u64t b0 = *(const u64t*)(wr);
            u64t b1 = *(const u64t*)(wr+2);
            u64t b2 = *(const u64t*)(wr+4);
            ffma2(acc[0][0], pa0, b0); ffma2(acc[0][1], pa0, b1); ffma2(acc[0][2], pa0, b2);
            ffma2(acc[1][0], pa1, b0); ffma2(acc[1][1], pa1, b1); ffma2(acc[1][2], pa1, b2);
        }
        // no trailing barrier: next iteration writes buf^1, whose last readers
        // all passed this iteration's barrier after finishing chunk ch-1.
    }

    // ---- epilogue: exchange accumulators via ws[0] (safe to reuse) ----
    #pragma unroll
    for (int i=0;i<2;i++){
        int m = 2*ty + i;
        #pragma unroll
        for (int p=0;p<3;p++){
            float2 v = upk2(acc[i][p]);
            *(float2*)&ws[0][m][6*tx + 2*p] = v;
        }
    }
    __syncthreads();

    #pragma unroll
    for (int q=0;q<4;q++){
        int m = (tid>>5) + q*8;
        int b = bb + m;
        float hr = ws[0][m][jl_e];
        float hz = ws[0][m][32 + jl_e];
        float hn = ws[0][m][64 + jl_e];
        float r = sigmoidf_(exr[q] + hr + br);
        float z = sigmoidf_(exz[q] + hz + bz);
        float n = tanhf(exn[q] + r*(hn + bn));
        bool valid = t < elen[q];
        float hv = (1.f - z)*n + z*ehp[q];
        h_next[(size_t)b*HH + jj] = valid ? hv : ehp[q];
        hidden[(size_t)b*(TT*HH) + (size_t)t*HH + jj] = valid ? hv : 0.f;
    }
}

// ---------------------------------------------------------------------------
// Kernel 3: pre[row,n] = sigmoid( hwt[row,:] . w1[n,:] + b1[n] )
// ---------------------------------------------------------------------------
__global__ __launch_bounds__(256) void gemm_pre(
    const float* __restrict__ hidden, const float* __restrict__ X,
    const float* __restrict__ W1, const float* __restrict__ b1,
    float* __restrict__ pre)
{
    __shared__ __align__(16) float As[32][68];
    __shared__ __align__(16) float Bs[32][68];
    const int bm = blockIdx.y*64;
    const int bn = blockIdx.x*64;
    const int tid = threadIdx.x;
    const int tx = tid & 15, ty = tid >> 4;
    u64t acc[4][2] = {};
    for (int k0 = 0; k0 < K1; k0 += 32){
        #pragma unroll
        for (int i=0;i<8;i++){
            int idx = tid + i*256;
            int kk = idx & 31, mm = idx >> 5;
            int k = k0 + kk;
            int row = bm + mm;
            int b = row / TM1;
            int tt = row - b*TM1;
            float v = 0.f;
            if (k < HH){
                v = hidden[(size_t)b*(TT*HH) + (size_t)tt*HH + k];
            } else if (k == HH){
                v = X[(size_t)(tt+1)*BB*DIN + (size_t)b*DIN]
                  - X[(size_t)tt*BB*DIN + (size_t)b*DIN];
            }
            As[kk][mm] = v;
        }
        #pragma unroll
        for (int i=0;i<8;i++){
            int idx = tid + i*256;
            int kk = idx & 31, nn = idx >> 5;
            Bs[kk][nn] = (k0+kk < K1) ? W1[(size_t)(bn+nn)*K1 + k0+kk] : 0.f;
        }
        __syncthreads();
        #pragma unroll
        for (int kk=0;kk<32;kk++){
            float4 a = *(const float4*)&As[kk][ty*4];
            ulonglong2 b = *(const ulonglong2*)&Bs[kk][tx*4];
            u64t pa0 = pk2(a.x,a.x), pa1 = pk2(a.y,a.y);
            u64t pa2 = pk2(a.z,a.z), pa3 = pk2(a.w,a.w);
            ffma2(acc[0][0], pa0, b.x); ffma2(acc[0][1], pa0, b.y);
            ffma2(acc[1][0], pa1, b.x); ffma2(acc[1][1], pa1, b.y);
            ffma2(acc[2][0], pa2, b.x); ffma2(acc[2][1], pa2, b.y);
            ffma2(acc[3][0], pa3, b.x); ffma2(acc[3][1], pa3, b.y);
        }
        __syncthreads();
    }
    #pragma unroll
    for (int i=0;i<4;i++){
        int row = bm + ty*4 + i;
        #pragma unroll
        for (int p=0;p<2;p++){
            float2 v = upk2(acc[i][p]);
            int n = bn + tx*4 + 2*p;
            pre[(size_t)row*N1 + n]     = sigmoidf_(v.x + b1[n]);
            pre[(size_t)row*N1 + n + 1] = sigmoidf_(v.y + b1[n+1]);
        }
    }
}

// ---------------------------------------------------------------------------
// Kernel 4: preds[row,d] = mask ? pre[row,:] . w2[d,:] + b2[d] : 0
// ---------------------------------------------------------------------------
__global__ __launch_bounds__(256) void gemm_preds(
    const float* __restrict__ pre, const float* __restrict__ W2,
    const float* __restrict__ b2, const int* __restrict__ lengths,
    float* __restrict__ out)
{
    __shared__ __align__(16) float As[32][68];
    __shared__ __align__(16) float Bs[32][68];
    const int bm = blockIdx.y*64;
    const int bn = blockIdx.x*64;
    const int tid = threadIdx.x;
    const int tx = tid & 15, ty = tid >> 4;
    u64t acc[4][2] = {};
    for (int k0 = 0; k0 < N1; k0 += 32){
        #pragma unroll
        for (int i=0;i<8;i++){
            int idx = tid + i*256;
            int kk = idx & 31, mm = idx >> 5;
            As[kk][mm] = pre[(size_t)(bm+mm)*N1 + k0+kk];
        }
        #pragma unroll
        for (int i=0;i<8;i++){
            int idx = tid + i*256;
            int kk = idx & 31, nn = idx >> 5;
            Bs[kk][nn] = W2[(size_t)(bn+nn)*N1 + k0+kk];
        }
        __syncthreads();
        #pragma unroll
        for (int kk=0;kk<32;kk++){
            float4 a = *(const float4*)&As[kk][ty*4];
            ulonglong2 b = *(const ulonglong2*)&Bs[kk][tx*4];
            u64t pa0 = pk2(a.x,a.x), pa1 = pk2(a.y,a.y);
            u64t pa2 = pk2(a.z,a.z), pa3 = pk2(a.w,a.w);
            ffma2(acc[0][0], pa0, b.x); ffma2(acc[0][1], pa0, b.y);
            ffma2(acc[1][0], pa1, b.x); ffma2(acc[1][1], pa1, b.y);
            ffma2(acc[2][0], pa2, b.x); ffma2(acc[2][1], pa2, b.y);
            ffma2(acc[3][0], pa3, b.x); ffma2(acc[3][1], pa3, b.y);
        }
        __syncthreads();
    }
    #pragma unroll
    for (int i=0;i<4;i++){
        int row = bm + ty*4 + i;
        int b = row / TM1;
        int tt = row - b*TM1;
        bool m = tt < (lengths[b] - 1);
        #pragma unroll
        for (int p=0;p<2;p++){
            float2 v = upk2(acc[i][p]);
            int n = bn + tx*4 + 2*p;
            out[(size_t)row*DOUT + n]     = m ? (v.x + b2[n])   : 0.f;
            out[(size_t)row*DOUT + n + 1] = m ? (v.y + b2[n+1]) : 0.f;
        }
    }
}

// ---------------------------------------------------------------------------
// Kernel 5: dist head + lengths passthrough
// ---------------------------------------------------------------------------
__global__ __launch_bounds__(256) void finalize_k(
    const float* __restrict__ h_last, const float* __restrict__ wp,
    const float* __restrict__ bp, const int* __restrict__ lengths,
    float* __restrict__ out)
{
    int b = threadIdx.x;
    if (b < BB){
        #pragma unroll
        for (int p=0;p<3;p++){
            float dot = 0.f;
            for (int h=0;h<HH;h++) dot += h_last[b*HH + h]*wp[p*HH + h];
            out[OFF_DIST + (size_t)b*3 + p] = expf(-(dot + bp[p]));
        }
        out[OFF_LEN + b] = (float)lengths[b];
    }
}

// ---------------------------------------------------------------------------
extern "C" void kernel_launch(void* const* d_in, const int* in_sizes, int n_in,
                              void* d_out, int out_size)
{
    const float* x    = (const float*)d_in[0];
    const float* h0   = (const float*)d_in[1];
    const int*   len  = (const int*)d_in[2];
    const float* w_ih = (const float*)d_in[3];
    const float* w_hh = (const float*)d_in[4];
    const float* b_ih = (const float*)d_in[5];
    const float* b_hh = (const float*)d_in[6];
    const float* w1   = (const float*)d_in[7];
    const float* b1   = (const float*)d_in[8];
    const float* w2   = (const float*)d_in[9];
    const float* b2   = (const float*)d_in[10];
    const float* wp   = (const float*)d_in[11];
    const float* bp   = (const float*)d_in[12];
    float* out = (float*)d_out;

    float *xw, *hidden, *hA, *hB, *pre;
    cudaGetSymbolAddress((void**)&xw,     g_xw);
    cudaGetSymbolAddress((void**)&hidden, g_hidden);
    cudaGetSymbolAddress((void**)&hA,     g_hA);
    cudaGetSymbolAddress((void**)&hB,     g_hB);
    cudaGetSymbolAddress((void**)&pre,    g_pre);

    // 1) input projection for all timesteps
    gemm_xw<<<dim3(GG/64, (TT*BB)/64), 256>>>(x, w_ih, b_ih, xw);

    // 2) sequential GRU with ping-pong h buffers
    const float* cur = h0;
    for (int t = 0; t < TT; t++){
        float* nxt = (t & 1) ? hB : hA;
        gru_step<<<dim3(16, 8), 256>>>(
            xw + (size_t)t*BB*GG, cur, nxt, hidden, w_hh, b_hh, len, t);
        cur = nxt;
    }

    // 3) MLP head
    gemm_pre<<<dim3(N1/64, M_PRE/64), 256>>>(hidden, x, w1, b1, pre);
    gemm_preds<<<dim3(DOUT/64, M_PRE/64), 256>>>(pre, w2, b2, len, out);

    // 4) distribution head + lengths passthrough  (t=255 wrote hB)
    finalize_k<<<1, 256>>>(hB, wp, bp, len, out);
}